// round 16
// baseline (speedup 1.0000x reference)
#include <cuda_runtime.h>
#include <cuda_fp16.h>
#include <math.h>
#include <stdint.h>

#define B_ 2
#define S_ 2048
#define NH_ 32
#define BS_ (B_*S_)

// ---------------- scratch (fp16 fragment buffers stored as u32) ----------------
__device__ float g_qkv[(size_t)BS_*3072];          // merged QKV projection output (f32)
__device__ float g_ao[(size_t)B_*NH_*S_*128];      // attn out (pre-diff, f32)
__device__ uint32_t g_hsp[(size_t)BS_*1024];       // hs A-frags (fp16)
__device__ uint32_t g_attp[(size_t)BS_*1024];      // diff/rms out A-frags (fp16)
__device__ uint32_t g_wqkvp[(size_t)3072*1024];    // packed B-frags: wq|wk|wv (fp16)
__device__ uint32_t g_wop[(size_t)2048*1024];      // packed B-frags: wo (fp16)
__device__ uint32_t g_qf[(size_t)2*32*128*4*128];  // Q A-frags (roped, scaled)
__device__ uint32_t g_kf[(size_t)2*8*256*2*128];   // K packed B-frags (roped)
__device__ uint32_t g_vf[(size_t)2*8*8*64*128];    // V packed B-frags
__device__ float g_lam;

// ---------------- helpers ----------------
__device__ __forceinline__ void mma_f16(float* d, const uint32_t* a, const uint32_t* b) {
    asm volatile(
        "mma.sync.aligned.m16n8k16.row.col.f32.f16.f16.f32 "
        "{%0,%1,%2,%3}, {%4,%5,%6,%7}, {%8,%9}, {%0,%1,%2,%3};\n"
        : "+f"(d[0]), "+f"(d[1]), "+f"(d[2]), "+f"(d[3])
        : "r"(a[0]), "r"(a[1]), "r"(a[2]), "r"(a[3]), "r"(b[0]), "r"(b[1]));
}

// ---------------- merged permute: hs->A-frags, wq|wk|wv->B-frags, wo->B-frags ----------------
__global__ void __launch_bounds__(256) permAll(
    const float* __restrict__ hs, const float* __restrict__ wq,
    const float* __restrict__ wk, const float* __restrict__ wv,
    const float* __restrict__ wo, __half* __restrict__ yA,
    __half* __restrict__ yQKV, __half* __restrict__ yWO) {
    size_t i = (size_t)blockIdx.x*256 + threadIdx.x;   // 9216*2048
    int col = (int)(i & 2047), row = (int)(i >> 11);
    if (row < 4096) {
        float v = hs[(size_t)row*2048 + col];
        int mt = row >> 4, r = row & 15, kt = col >> 4, kk = col & 15;
        int reg = (r >> 3) + 2*(kk >> 3);
        int lane = (r & 7)*4 + ((kk & 7) >> 1);
        yA[((((size_t)mt*128 + kt)*32 + lane)*4 + reg)*2 + (kk & 1)] = __float2half_rn(v);
    } else if (row < 7168) {
        int wrow = row - 4096;
        const float* src; int srow;
        if (wrow < 2048)      { src = wq; srow = wrow; }
        else if (wrow < 2560) { src = wk; srow = wrow - 2048; }
        else                  { src = wv; srow = wrow - 2560; }
        float v = src[(size_t)srow*2048 + col];
        int ntg = wrow >> 3, g = wrow & 7;
        int kt = col >> 4, kk = col & 15;
        int ktp = kt >> 1, par = kt & 1;
        int reg = kk >> 3, lane = g*4 + ((kk & 7) >> 1);
        yQKV[((((size_t)ntg*64 + ktp)*32 + lane)*4 + par*2 + reg)*2 + (kk & 1)] = __float2half_rn(v);
    } else {
        int wrow = row - 7168;
        float v = wo[(size_t)wrow*2048 + col];
        int ntg = wrow >> 3, g = wrow & 7;
        int kt = col >> 4, kk = col & 15;
        int ktp = kt >> 1, par = kt & 1;
        int reg = kk >> 3, lane = g*4 + ((kk & 7) >> 1);
        yWO[((((size_t)ntg*64 + ktp)*32 + lane)*4 + par*2 + reg)*2 + (kk & 1)] = __float2half_rn(v);
    }
}

// ---------------- lambda scalar ----------------
__global__ void lam_kernel(const float* __restrict__ lq1, const float* __restrict__ lk1,
                           const float* __restrict__ lq2, const float* __restrict__ lk2) {
    int t = threadIdx.x;
    float s1 = lq1[t]*lk1[t] + lq1[t+32]*lk1[t+32];
    float s2 = lq2[t]*lk2[t] + lq2[t+32]*lk2[t+32];
    #pragma unroll
    for (int off = 16; off >= 1; off >>= 1) {
        s1 += __shfl_xor_sync(0xffffffffu, s1, off);
        s2 += __shfl_xor_sync(0xffffffffu, s2, off);
    }
    if (t == 0) {
        float li = 0.8f - 0.6f*expf(-0.3f);
        g_lam = expf(s1) - expf(s2) + li;
    }
}

// ---------------- smem-free fragment-direct fp16 GEMM (R9 config) ----------------
__global__ void __launch_bounds__(256) gemm_direct(
    const uint32_t* __restrict__ A, const uint32_t* __restrict__ Bw,
    float* __restrict__ C, int N) {
    const int tid = threadIdx.x, lane = tid & 31, warp = tid >> 5;
    const int wm = warp >> 2, wn = warp & 3;
    const int m0 = blockIdx.y << 7, n0 = blockIdx.x << 7;
    const uint32_t* Ap = A + (size_t)(blockIdx.y*8 + wm*4)*16384 + lane*4;
    const uint32_t* Bp = Bw + (size_t)(blockIdx.x*16 + wn*4)*8192 + lane*4;

    float acc[4][4][4];
    #pragma unroll
    for (int mt = 0; mt < 4; mt++)
        #pragma unroll
        for (int nt = 0; nt < 4; nt++)
            #pragma unroll
            for (int r = 0; r < 4; r++) acc[mt][nt][r] = 0.f;

    #pragma unroll 2
    for (int ktp = 0; ktp < 64; ktp++) {
        uint32_t af[4][2][4], bf[4][4];
        #pragma unroll
        for (int mt = 0; mt < 4; mt++) {
            *(uint4*)af[mt][0] = *(const uint4*)(Ap + (size_t)mt*16384 + (2*ktp)*128);
            *(uint4*)af[mt][1] = *(const uint4*)(Ap + (size_t)mt*16384 + (2*ktp+1)*128);
        }
        #pragma unroll
        for (int nt = 0; nt < 4; nt++)
            *(uint4*)bf[nt] = *(const uint4*)(Bp + (size_t)nt*8192 + ktp*128);
        #pragma unroll
        for (int mt = 0; mt < 4; mt++)
            #pragma unroll
            for (int nt = 0; nt < 4; nt++) {
                mma_f16(acc[mt][nt], af[mt][0], &bf[nt][0]);
                mma_f16(acc[mt][nt], af[mt][1], &bf[nt][2]);
            }
    }

    const int g = lane >> 2, t = lane & 3;
    #pragma unroll
    for (int mt = 0; mt < 4; mt++) {
        #pragma unroll
        for (int nt = 0; nt < 4; nt++) {
            size_t r0 = (size_t)(m0 + wm*64 + mt*16 + g)*N + n0 + wn*32 + nt*8 + 2*t;
            *(float2*)&C[r0]               = make_float2(acc[mt][nt][0], acc[mt][nt][1]);
            *(float2*)&C[r0 + (size_t)8*N] = make_float2(acc[mt][nt][2], acc[mt][nt][3]);
        }
    }
}

// ---------------- fused rope + fragment permute for Q, K, V ----------------
__global__ void __launch_bounds__(256) fragqkv_k(
    const float* __restrict__ x, const float* __restrict__ cs,
    const float* __restrict__ sn, __half* __restrict__ yq,
    __half* __restrict__ yk, __half* __restrict__ yv) {
    int idx = blockIdx.x*256 + threadIdx.x;   // BS_*1792 threads
    int u  = idx % 1792;
    int bs = idx / 1792;
    int b = bs >> 11, s = bs & 2047;

    if (u < 1024) {
        int d = u & 31, h = u >> 5;
        const float* row = x + (size_t)bs*3072 + h*64;
        float c0 = cs[(size_t)bs*64 + d],      s0 = sn[(size_t)bs*64 + d];
        float c1 = cs[(size_t)bs*64 + d + 32], s1 = sn[(size_t)bs*64 + d + 32];
        float x0 = row[d], x1 = row[d+32];
        float y0 = (x0*c0 - x1*s0) * 0.125f;
        float y1 = (x1*c1 + x0*s1) * 0.125f;
        int mt = s >> 4, r = s & 15;
        size_t base = ((size_t)(b*32 + h)*128 + mt)*4;
        #pragma unroll
        for (int j = 0; j < 2; j++) {
            int c = (j == 0) ? d : d + 32;
            float v = (j == 0) ? y0 : y1;
            int kt = c >> 4, kk = c & 15;
            int reg = (r >> 3) + 2*(kk >> 3);
            int lane = (r & 7)*4 + ((kk & 7) >> 1);
            yq[(((base + kt)*32 + lane)*4 + reg)*2 + (kk & 1)] = __float2half_rn(v);
        }
    } else if (u < 1280) {
        int v2 = u - 1024;
        int d = v2 & 31, kv = v2 >> 5;
        const float* row = x + (size_t)bs*3072 + 2048 + kv*64;
        float c0 = cs[(size_t)bs*64 + d],      s0 = sn[(size_t)bs*64 + d];
        float c1 = cs[(size_t)bs*64 + d + 32], s1 = sn[(size_t)bs*64 + d + 32];
        float x0 = row[d], x1 = row[d+32];
        float y0 = x0*c0 - x1*s0;
        float y1 = x1*c1 + x0*s1;
        int ntg = s >> 3, g = s & 7;
        size_t base = ((size_t)(b*8 + kv)*256 + ntg)*2;
        #pragma unroll
        for (int j = 0; j < 2; j++) {
            int c = (j == 0) ? d : d + 32;
            float v = (j == 0) ? y0 : y1;
            int kt = c >> 4, kk = c & 15;
            int ktp = kt >> 1, par = kt & 1;
            int reg = kk >> 3, lane = g*4 + ((kk & 7) >> 1);
            yk[(((base + ktp)*32 + lane)*4 + par*2 + reg)*2 + (kk & 1)] = __float2half_rn(v);
        }
    } else {
        int v2 = u - 1280;
        int d = v2 & 63, kv = v2 >> 6;
        float val = x[(size_t)bs*3072 + 2560 + kv*64 + d];
        int ntg = d >> 3, g = d & 7;
        int kt = s >> 4, kk = s & 15;
        int ktp = kt >> 1, par = kt & 1;
        int reg = kk >> 3, lane = g*4 + ((kk & 7) >> 1);
        yv[(((((size_t)(b*8 + kv)*8 + ntg)*64 + ktp)*32 + lane)*4 + par*2 + reg)*2 + (kk & 1)] =
            __float2half_rn(val);
    }
}

// ---------------- fragment-direct fp16 flash attention ----------------
// 128-row Q tile, 8 warps, 256 threads; K loop-carried pipeline; V prefetch.
// grid (16 qtiles, 32 heads, 2 batch)
__global__ void __launch_bounds__(256) attn_direct(
    const uint32_t* __restrict__ qf, const uint32_t* __restrict__ kf,
    const uint32_t* __restrict__ vf, float* __restrict__ ao) {
    const int tid = threadIdx.x, lane = tid & 31, w = tid >> 5;
    const int g = lane >> 2, t = lane & 3;
    const int qt = gridDim.x - 1 - blockIdx.x;   // heavy tiles first
    const int h = blockIdx.y, b = blockIdx.z;
    const int kvq = h >> 2;
    const int j1 = (h & 15) >> 2, j2 = j1 + 4;
    const int nkt = 2*qt + 1;                    // last 64-wide k-tile index

    uint32_t qfr[4][4];
    {
        const uint32_t* qp = qf + ((size_t)(b*32 + h)*128 + qt*8 + w)*512 + lane*4;
        #pragma unroll
        for (int kt = 0; kt < 4; kt++)
            *(uint4*)qfr[kt] = *(const uint4*)(qp + kt*128);
    }
    const uint32_t* kbase = kf + (size_t)(b*8 + kvq)*65536 + lane*4;
    const uint32_t* vbase = vf + (size_t)b*8*65536 + lane*4;

    float m_[2], l_[2], O[16][4];
    m_[0] = m_[1] = -1e30f; l_[0] = l_[1] = 0.f;
    #pragma unroll
    for (int nt = 0; nt < 16; nt++)
        #pragma unroll
        for (int r = 0; r < 4; r++) O[nt][r] = 0.f;

    // loop-carried K fragments: preload ktt=0
    uint32_t kbf[2][8][4];
    #pragma unroll
    for (int ktp = 0; ktp < 2; ktp++)
        #pragma unroll
        for (int nt = 0; nt < 8; nt++)
            *(uint4*)kbf[ktp][nt] = *(const uint4*)(kbase + ((size_t)nt*2 + ktp)*128);

    for (int ktt = 0; ktt <= nkt; ktt++) {
        // 1. S = Q K^T (ktp outer, nt inner — same accumulation order)
        float s[8][4];
        #pragma unroll
        for (int nt = 0; nt < 8; nt++)
            #pragma unroll
            for (int r = 0; r < 4; r++) s[nt][r] = 0.f;
        #pragma unroll
        for (int ktp = 0; ktp < 2; ktp++)
            #pragma unroll
            for (int nt = 0; nt < 8; nt++) {
                mma_f16(s[nt], qfr[2*ktp],   &kbf[ktp][nt][0]);
                mma_f16(s[nt], qfr[2*ktp+1], &kbf[ktp][nt][2]);
            }

        // 2. prefetch V ktp0 — in flight across the whole softmax phase
        uint32_t vbf0[16][4];
        #pragma unroll
        for (int nt = 0; nt < 16; nt++) {
            int kvh = (nt < 8) ? j1 : j2;
            *(uint4*)vbf0[nt] = *(const uint4*)(vbase +
                (((size_t)kvh*8 + (nt & 7))*64 + ktt*2)*128);
        }

        // causal mask (only last two k-tiles can cross the diagonal)
        if (ktt >= 2*qt) {
            int rowg = qt*128 + w*16 + g;
            #pragma unroll
            for (int nt = 0; nt < 8; nt++)
                #pragma unroll
                for (int rr = 0; rr < 2; rr++)
                    #pragma unroll
                    for (int cc = 0; cc < 2; cc++)
                        if (ktt*64 + nt*8 + 2*t + cc > rowg + rr*8)
                            s[nt][rr*2+cc] = -1e30f;
        }

        // 3. online softmax (covers vbf0 latency)
        #pragma unroll
        for (int rr = 0; rr < 2; rr++) {
            float rm = -1e30f;
            #pragma unroll
            for (int nt = 0; nt < 8; nt++)
                rm = fmaxf(rm, fmaxf(s[nt][rr*2], s[nt][rr*2+1]));
            rm = fmaxf(rm, __shfl_xor_sync(0xffffffffu, rm, 1));
            rm = fmaxf(rm, __shfl_xor_sync(0xffffffffu, rm, 2));
            float mn = fmaxf(m_[rr], rm);
            float f  = __expf(m_[rr] - mn);
            float rs = 0.f;
            #pragma unroll
            for (int nt = 0; nt < 8; nt++) {
                s[nt][rr*2]   = __expf(s[nt][rr*2]   - mn);
                s[nt][rr*2+1] = __expf(s[nt][rr*2+1] - mn);
                rs += s[nt][rr*2] + s[nt][rr*2+1];
            }
            rs += __shfl_xor_sync(0xffffffffu, rs, 1);
            rs += __shfl_xor_sync(0xffffffffu, rs, 2);
            l_[rr] = l_[rr]*f + rs;
            m_[rr] = mn;
            #pragma unroll
            for (int nt = 0; nt < 16; nt++) { O[nt][rr*2] *= f; O[nt][rr*2+1] *= f; }
        }

        // 4. prefetch V ktp1 — covered by pf convert + PV ktp0
        uint32_t vbf1[16][4];
        #pragma unroll
        for (int nt = 0; nt < 16; nt++) {
            int kvh = (nt < 8) ? j1 : j2;
            *(uint4*)vbf1[nt] = *(const uint4*)(vbase +
                (((size_t)kvh*8 + (nt & 7))*64 + ktt*2 + 1)*128);
        }

        // 5. S C-frag -> P A-frag (register identity)
        uint32_t pf[4][4];
        #pragma unroll
        for (int nt = 0; nt < 8; nt++)
            #pragma unroll
            for (int rr = 0; rr < 2; rr++) {
                __half2 hv = __floats2half2_rn(s[nt][rr*2], s[nt][rr*2+1]);
                pf[nt >> 1][rr + 2*(nt & 1)] = *(uint32_t*)&hv;
            }

        // 6. O += P @ V ktp0 (vbf0 dies here)
        #pragma unroll
        for (int nt = 0; nt < 16; nt++) {
            mma_f16(O[nt], pf[0], &vbf0[nt][0]);
            mma_f16(O[nt], pf[1], &vbf0[nt][2]);
        }

        // 7. prefetch next-iteration K (clamped; covered by PV ktp1 + loop top)
        {
            int ktn = (ktt < nkt) ? ktt + 1 : ktt;
            #pragma unroll
            for (int ktp = 0; ktp < 2; ktp++)
                #pragma unroll
                for (int nt = 0; nt < 8; nt++)
                    *(uint4*)kbf[ktp][nt] =
                        *(const uint4*)(kbase + ((size_t)(ktn*8 + nt)*2 + ktp)*128);
        }

        // 8. O += P @ V ktp1
        #pragma unroll
        for (int nt = 0; nt < 16; nt++) {
            mma_f16(O[nt], pf[2], &vbf1[nt][0]);
            mma_f16(O[nt], pf[3], &vbf1[nt][2]);
        }
    }

    #pragma unroll
    for (int rr = 0; rr < 2; rr++) {
        float inv = 1.0f / l_[rr];
        size_t base = (((size_t)b*NH_ + h)*S_ + (size_t)qt*128 + w*16 + g + rr*8)*128;
        #pragma unroll
        for (int nt = 0; nt < 16; nt++)
            *(float2*)&ao[base + nt*8 + 2*t] =
                make_float2(O[nt][rr*2]*inv, O[nt][rr*2+1]*inv);
    }
}

// ---------------- differential combine + RMS norm -> fp16 A-frag layout ----------------
__global__ void __launch_bounds__(128) diff_rms_kernel(
    const float* __restrict__ ao, __half* __restrict__ outp) {
    __shared__ float red[4];
    int blk = blockIdx.x;
    int h  = blk & 15;
    int bs = blk >> 4;
    int b  = bs >> 11;
    int s  = bs & 2047;
    int t  = threadIdx.x;
    const float* a1 = ao + (((size_t)b*32 + h)*S_ + s)*128;
    const float* a2 = ao + (((size_t)b*32 + h + 16)*S_ + s)*128;
    float lam = g_lam;
    float x = a1[t] - lam*a2[t];
    float ss = x*x;
    #pragma unroll
    for (int off = 16; off >= 1; off >>= 1) ss += __shfl_xor_sync(0xffffffffu, ss, off);
    if ((t & 31) == 0) red[t >> 5] = ss;
    __syncthreads();
    float tot = red[0] + red[1] + red[2] + red[3];
    float r = rsqrtf(tot*(1.0f/128.0f) + 1e-6f);
    float li = 0.8f - 0.6f*expf(-0.3f);
    float val = (1.0f - li) * x * r;
    int row = bs, col = h*128 + t;
    int mt = row >> 4, rr = row & 15, kt = col >> 4, kk = col & 15;
    int reg = (rr >> 3) + 2*(kk >> 3);
    int lane = (rr & 7)*4 + ((kk & 7) >> 1);
    outp[((((size_t)mt*128 + kt)*32 + lane)*4 + reg)*2 + (kk & 1)] = __float2half_rn(val);
}

// ---------------- launch ----------------
extern "C" void kernel_launch(void* const* d_in, const int* in_sizes, int n_in,
                              void* d_out, int out_size) {
    const float* hs  = (const float*)d_in[0];
    const float* cs  = (const float*)d_in[1];
    const float* sn  = (const float*)d_in[2];
    const float* wq  = (const float*)d_in[4];
    const float* wk  = (const float*)d_in[5];
    const float* wv  = (const float*)d_in[6];
    const float* wo  = (const float*)d_in[7];
    const float* lq1 = (const float*)d_in[8];
    const float* lk1 = (const float*)d_in[9];
    const float* lq2 = (const float*)d_in[10];
    const float* lk2 = (const float*)d_in[11];
    float* out = (float*)d_out;

    float *qkvb, *aob;
    uint32_t *hsp, *attp, *wqkvp, *wop, *qfp, *kfp, *vfp;
    cudaGetSymbolAddress((void**)&qkvb, g_qkv);
    cudaGetSymbolAddress((void**)&aob,  g_ao);
    cudaGetSymbolAddress((void**)&hsp,  g_hsp);
    cudaGetSymbolAddress((void**)&attp, g_attp);
    cudaGetSymbolAddress((void**)&wqkvp, g_wqkvp);
    cudaGetSymbolAddress((void**)&wop,  g_wop);
    cudaGetSymbolAddress((void**)&qfp,  g_qf);
    cudaGetSymbolAddress((void**)&kfp,  g_kf);
    cudaGetSymbolAddress((void**)&vfp,  g_vf);

    // launch order: attn_direct is launch #4 -> profiled slot
    permAll<<<9216*2048/256, 256>>>(hs, wq, wk, wv, wo,
        (__half*)hsp, (__half*)wqkvp, (__half*)wop);

    dim3 gqkv(3072/128, BS_/128);
    gemm_direct<<<gqkv, 256>>>(hsp, wqkvp, qkvb, 3072);

    fragqkv_k<<<BS_*1792/256, 256>>>(qkvb, cs, sn,
        (__half*)qfp, (__half*)kfp, (__half*)vfp);

    dim3 ga(S_/128, NH_, B_);
    attn_direct<<<ga, 256>>>(qfp, kfp, vfp, aob);

    lam_kernel<<<1, 32>>>(lq1, lk1, lq2, lk2);

    diff_rms_kernel<<<BS_*16, 128>>>(aob, (__half*)attp);

    dim3 go(2048/128, BS_/128);
    gemm_direct<<<go, 256>>>(attp, wop, out, 2048);
}

// round 17
// speedup vs baseline: 1.0718x; 1.0718x over previous
#include <cuda_runtime.h>
#include <cuda_fp16.h>
#include <math.h>
#include <stdint.h>

#define B_ 2
#define S_ 2048
#define NH_ 32
#define BS_ (B_*S_)

// ---------------- scratch (fp16 fragment buffers stored as u32) ----------------
__device__ float g_qkv[(size_t)BS_*3072];          // merged QKV projection output (f32)
__device__ float g_ao[(size_t)B_*NH_*S_*128];      // attn out (pre-diff, f32)
__device__ uint32_t g_hsp[(size_t)BS_*1024];       // hs A-frags (fp16)
__device__ uint32_t g_attp[(size_t)BS_*1024];      // diff/rms out A-frags (fp16)
__device__ uint32_t g_wqkvp[(size_t)3072*1024];    // packed B-frags: wq|wk|wv (fp16)
__device__ uint32_t g_wop[(size_t)2048*1024];      // packed B-frags: wo (fp16)
__device__ uint32_t g_qf[(size_t)2*32*128*4*128];  // Q A-frags (roped, scaled)
__device__ uint32_t g_kf[(size_t)2*8*256*2*128];   // K packed B-frags (roped)
__device__ uint32_t g_vf[(size_t)2*8*8*64*128];    // V packed B-frags
__device__ float g_lam;

// ---------------- helpers ----------------
__device__ __forceinline__ void mma_f16(float* d, const uint32_t* a, const uint32_t* b) {
    asm volatile(
        "mma.sync.aligned.m16n8k16.row.col.f32.f16.f16.f32 "
        "{%0,%1,%2,%3}, {%4,%5,%6,%7}, {%8,%9}, {%0,%1,%2,%3};\n"
        : "+f"(d[0]), "+f"(d[1]), "+f"(d[2]), "+f"(d[3])
        : "r"(a[0]), "r"(a[1]), "r"(a[2]), "r"(a[3]), "r"(b[0]), "r"(b[1]));
}

// ---------------- merged permute (half2-paired: one u32 store per thread) ----------------
// col pair (kk, kk+1) shares one output u32 in every layout used here.
__global__ void __launch_bounds__(256) permAll(
    const float* __restrict__ hs, const float* __restrict__ wq,
    const float* __restrict__ wk, const float* __restrict__ wv,
    const float* __restrict__ wo, uint32_t* __restrict__ yA,
    uint32_t* __restrict__ yQKV, uint32_t* __restrict__ yWO) {
    size_t i = (size_t)blockIdx.x*256 + threadIdx.x;   // 9216*1024
    int c2 = (int)(i & 1023), row = (int)(i >> 10);
    int col = c2 << 1;
    if (row < 4096) {
        float2 v = *(const float2*)(hs + (size_t)row*2048 + col);
        __half2 hv = __floats2half2_rn(v.x, v.y);
        int mt = row >> 4, r = row & 15, kt = col >> 4, kk = col & 15;
        int reg = (r >> 3) + 2*(kk >> 3);
        int lane = (r & 7)*4 + ((kk & 7) >> 1);
        yA[(((size_t)mt*128 + kt)*32 + lane)*4 + reg] = *(uint32_t*)&hv;
    } else if (row < 7168) {
        int wrow = row - 4096;
        const float* src; int srow;
        if (wrow < 2048)      { src = wq; srow = wrow; }
        else if (wrow < 2560) { src = wk; srow = wrow - 2048; }
        else                  { src = wv; srow = wrow - 2560; }
        float2 v = *(const float2*)(src + (size_t)srow*2048 + col);
        __half2 hv = __floats2half2_rn(v.x, v.y);
        int ntg = wrow >> 3, g = wrow & 7;
        int kt = col >> 4, kk = col & 15;
        int ktp = kt >> 1, par = kt & 1;
        int reg = kk >> 3, lane = g*4 + ((kk & 7) >> 1);
        yQKV[(((size_t)ntg*64 + ktp)*32 + lane)*4 + par*2 + reg] = *(uint32_t*)&hv;
    } else {
        int wrow = row - 7168;
        float2 v = *(const float2*)(wo + (size_t)wrow*2048 + col);
        __half2 hv = __floats2half2_rn(v.x, v.y);
        int ntg = wrow >> 3, g = wrow & 7;
        int kt = col >> 4, kk = col & 15;
        int ktp = kt >> 1, par = kt & 1;
        int reg = kk >> 3, lane = g*4 + ((kk & 7) >> 1);
        yWO[(((size_t)ntg*64 + ktp)*32 + lane)*4 + par*2 + reg] = *(uint32_t*)&hv;
    }
}

// ---------------- lambda scalar ----------------
__global__ void lam_kernel(const float* __restrict__ lq1, const float* __restrict__ lk1,
                           const float* __restrict__ lq2, const float* __restrict__ lk2) {
    int t = threadIdx.x;
    float s1 = lq1[t]*lk1[t] + lq1[t+32]*lk1[t+32];
    float s2 = lq2[t]*lk2[t] + lq2[t+32]*lk2[t+32];
    #pragma unroll
    for (int off = 16; off >= 1; off >>= 1) {
        s1 += __shfl_xor_sync(0xffffffffu, s1, off);
        s2 += __shfl_xor_sync(0xffffffffu, s2, off);
    }
    if (t == 0) {
        float li = 0.8f - 0.6f*expf(-0.3f);
        g_lam = expf(s1) - expf(s2) + li;
    }
}

// ---------------- smem-free fragment-direct fp16 GEMM (R9 config) ----------------
__global__ void __launch_bounds__(256) gemm_direct(
    const uint32_t* __restrict__ A, const uint32_t* __restrict__ Bw,
    float* __restrict__ C, int N) {
    const int tid = threadIdx.x, lane = tid & 31, warp = tid >> 5;
    const int wm = warp >> 2, wn = warp & 3;
    const int m0 = blockIdx.y << 7, n0 = blockIdx.x << 7;
    const uint32_t* Ap = A + (size_t)(blockIdx.y*8 + wm*4)*16384 + lane*4;
    const uint32_t* Bp = Bw + (size_t)(blockIdx.x*16 + wn*4)*8192 + lane*4;

    float acc[4][4][4];
    #pragma unroll
    for (int mt = 0; mt < 4; mt++)
        #pragma unroll
        for (int nt = 0; nt < 4; nt++)
            #pragma unroll
            for (int r = 0; r < 4; r++) acc[mt][nt][r] = 0.f;

    #pragma unroll 2
    for (int ktp = 0; ktp < 64; ktp++) {
        uint32_t af[4][2][4], bf[4][4];
        #pragma unroll
        for (int mt = 0; mt < 4; mt++) {
            *(uint4*)af[mt][0] = *(const uint4*)(Ap + (size_t)mt*16384 + (2*ktp)*128);
            *(uint4*)af[mt][1] = *(const uint4*)(Ap + (size_t)mt*16384 + (2*ktp+1)*128);
        }
        #pragma unroll
        for (int nt = 0; nt < 4; nt++)
            *(uint4*)bf[nt] = *(const uint4*)(Bp + (size_t)nt*8192 + ktp*128);
        #pragma unroll
        for (int mt = 0; mt < 4; mt++)
            #pragma unroll
            for (int nt = 0; nt < 4; nt++) {
                mma_f16(acc[mt][nt], af[mt][0], &bf[nt][0]);
                mma_f16(acc[mt][nt], af[mt][1], &bf[nt][2]);
            }
    }

    const int g = lane >> 2, t = lane & 3;
    #pragma unroll
    for (int mt = 0; mt < 4; mt++) {
        #pragma unroll
        for (int nt = 0; nt < 4; nt++) {
            size_t r0 = (size_t)(m0 + wm*64 + mt*16 + g)*N + n0 + wn*32 + nt*8 + 2*t;
            *(float2*)&C[r0]               = make_float2(acc[mt][nt][0], acc[mt][nt][1]);
            *(float2*)&C[r0 + (size_t)8*N] = make_float2(acc[mt][nt][2], acc[mt][nt][3]);
        }
    }
}

// ---------------- fused rope + fragment permute for Q, K, V ----------------
__global__ void __launch_bounds__(256) fragqkv_k(
    const float* __restrict__ x, const float* __restrict__ cs,
    const float* __restrict__ sn, __half* __restrict__ yq,
    __half* __restrict__ yk, __half* __restrict__ yv) {
    int idx = blockIdx.x*256 + threadIdx.x;   // BS_*1792 threads
    int u  = idx % 1792;
    int bs = idx / 1792;
    int b = bs >> 11, s = bs & 2047;

    if (u < 1024) {
        int d = u & 31, h = u >> 5;
        const float* row = x + (size_t)bs*3072 + h*64;
        float c0 = cs[(size_t)bs*64 + d],      s0 = sn[(size_t)bs*64 + d];
        float c1 = cs[(size_t)bs*64 + d + 32], s1 = sn[(size_t)bs*64 + d + 32];
        float x0 = row[d], x1 = row[d+32];
        float y0 = (x0*c0 - x1*s0) * 0.125f;
        float y1 = (x1*c1 + x0*s1) * 0.125f;
        int mt = s >> 4, r = s & 15;
        size_t base = ((size_t)(b*32 + h)*128 + mt)*4;
        #pragma unroll
        for (int j = 0; j < 2; j++) {
            int c = (j == 0) ? d : d + 32;
            float v = (j == 0) ? y0 : y1;
            int kt = c >> 4, kk = c & 15;
            int reg = (r >> 3) + 2*(kk >> 3);
            int lane = (r & 7)*4 + ((kk & 7) >> 1);
            yq[(((base + kt)*32 + lane)*4 + reg)*2 + (kk & 1)] = __float2half_rn(v);
        }
    } else if (u < 1280) {
        int v2 = u - 1024;
        int d = v2 & 31, kv = v2 >> 5;
        const float* row = x + (size_t)bs*3072 + 2048 + kv*64;
        float c0 = cs[(size_t)bs*64 + d],      s0 = sn[(size_t)bs*64 + d];
        float c1 = cs[(size_t)bs*64 + d + 32], s1 = sn[(size_t)bs*64 + d + 32];
        float x0 = row[d], x1 = row[d+32];
        float y0 = x0*c0 - x1*s0;
        float y1 = x1*c1 + x0*s1;
        int ntg = s >> 3, g = s & 7;
        size_t base = ((size_t)(b*8 + kv)*256 + ntg)*2;
        #pragma unroll
        for (int j = 0; j < 2; j++) {
            int c = (j == 0) ? d : d + 32;
            float v = (j == 0) ? y0 : y1;
            int kt = c >> 4, kk = c & 15;
            int ktp = kt >> 1, par = kt & 1;
            int reg = kk >> 3, lane = g*4 + ((kk & 7) >> 1);
            yk[(((base + ktp)*32 + lane)*4 + par*2 + reg)*2 + (kk & 1)] = __float2half_rn(v);
        }
    } else {
        int v2 = u - 1280;
        int d = v2 & 63, kv = v2 >> 6;
        float val = x[(size_t)bs*3072 + 2560 + kv*64 + d];
        int ntg = d >> 3, g = d & 7;
        int kt = s >> 4, kk = s & 15;
        int ktp = kt >> 1, par = kt & 1;
        int reg = kk >> 3, lane = g*4 + ((kk & 7) >> 1);
        yv[(((((size_t)(b*8 + kv)*8 + ntg)*64 + ktp)*32 + lane)*4 + par*2 + reg)*2 + (kk & 1)] =
            __float2half_rn(val);
    }
}

// ---------------- fragment-direct fp16 flash attention (R15 config) ----------------
// 64-row Q tile, 4 warps, grid (32 qtiles, 32 heads, 2 batch); K loop-carried.
__global__ void __launch_bounds__(128) attn_direct(
    const uint32_t* __restrict__ qf, const uint32_t* __restrict__ kf,
    const uint32_t* __restrict__ vf, float* __restrict__ ao) {
    const int tid = threadIdx.x, lane = tid & 31, w = tid >> 5;
    const int g = lane >> 2, t = lane & 3;
    const int qt = gridDim.x - 1 - blockIdx.x;   // heavy tiles first
    const int h = blockIdx.y, b = blockIdx.z;
    const int kvq = h >> 2;
    const int j1 = (h & 15) >> 2, j2 = j1 + 4;

    uint32_t qfr[4][4];
    {
        const uint32_t* qp = qf + ((size_t)(b*32 + h)*128 + qt*4 + w)*512 + lane*4;
        #pragma unroll
        for (int kt = 0; kt < 4; kt++)
            *(uint4*)qfr[kt] = *(const uint4*)(qp + kt*128);
    }
    const uint32_t* kbase = kf + (size_t)(b*8 + kvq)*65536 + lane*4;
    const uint32_t* vbase = vf + (size_t)b*8*65536 + lane*4;

    float m_[2], l_[2], O[16][4];
    m_[0] = m_[1] = -1e30f; l_[0] = l_[1] = 0.f;
    #pragma unroll
    for (int nt = 0; nt < 16; nt++)
        #pragma unroll
        for (int r = 0; r < 4; r++) O[nt][r] = 0.f;

    // loop-carried K fragments: preload kt=0
    uint32_t kbf[2][8][4];
    #pragma unroll
    for (int ktp = 0; ktp < 2; ktp++)
        #pragma unroll
        for (int nt = 0; nt < 8; nt++)
            *(uint4*)kbf[ktp][nt] = *(const uint4*)(kbase + ((size_t)nt*2 + ktp)*128);

    for (int kt = 0; kt <= qt; kt++) {
        // 1. S = Q K^T
        float s[8][4];
        #pragma unroll
        for (int nt = 0; nt < 8; nt++)
            #pragma unroll
            for (int r = 0; r < 4; r++) s[nt][r] = 0.f;
        #pragma unroll
        for (int ktp = 0; ktp < 2; ktp++)
            #pragma unroll
            for (int nt = 0; nt < 8; nt++) {
                mma_f16(s[nt], qfr[2*ktp],   &kbf[ktp][nt][0]);
                mma_f16(s[nt], qfr[2*ktp+1], &kbf[ktp][nt][2]);
            }

        // 2. prefetch V ktp0
        uint32_t vbf0[16][4];
        #pragma unroll
        for (int nt = 0; nt < 16; nt++) {
            int kvh = (nt < 8) ? j1 : j2;
            *(uint4*)vbf0[nt] = *(const uint4*)(vbase +
                (((size_t)kvh*8 + (nt & 7))*64 + kt*2)*128);
        }

        if (kt == qt) {
            #pragma unroll
            for (int nt = 0; nt < 8; nt++)
                #pragma unroll
                for (int rr = 0; rr < 2; rr++)
                    #pragma unroll
                    for (int cc = 0; cc < 2; cc++)
                        if (nt*8 + 2*t + cc > w*16 + g + rr*8)
                            s[nt][rr*2+cc] = -1e30f;
        }

        // 3. online softmax
        #pragma unroll
        for (int rr = 0; rr < 2; rr++) {
            float rm = -1e30f;
            #pragma unroll
            for (int nt = 0; nt < 8; nt++)
                rm = fmaxf(rm, fmaxf(s[nt][rr*2], s[nt][rr*2+1]));
            rm = fmaxf(rm, __shfl_xor_sync(0xffffffffu, rm, 1));
            rm = fmaxf(rm, __shfl_xor_sync(0xffffffffu, rm, 2));
            float mn = fmaxf(m_[rr], rm);
            float f  = __expf(m_[rr] - mn);
            float rs = 0.f;
            #pragma unroll
            for (int nt = 0; nt < 8; nt++) {
                s[nt][rr*2]   = __expf(s[nt][rr*2]   - mn);
                s[nt][rr*2+1] = __expf(s[nt][rr*2+1] - mn);
                rs += s[nt][rr*2] + s[nt][rr*2+1];
            }
            rs += __shfl_xor_sync(0xffffffffu, rs, 1);
            rs += __shfl_xor_sync(0xffffffffu, rs, 2);
            l_[rr] = l_[rr]*f + rs;
            m_[rr] = mn;
            #pragma unroll
            for (int nt = 0; nt < 16; nt++) { O[nt][rr*2] *= f; O[nt][rr*2+1] *= f; }
        }

        // 4. prefetch V ktp1
        uint32_t vbf1[16][4];
        #pragma unroll
        for (int nt = 0; nt < 16; nt++) {
            int kvh = (nt < 8) ? j1 : j2;
            *(uint4*)vbf1[nt] = *(const uint4*)(vbase +
                (((size_t)kvh*8 + (nt & 7))*64 + kt*2 + 1)*128);
        }

        // 5. S C-frag -> P A-frag
        uint32_t pf[4][4];
        #pragma unroll
        for (int nt = 0; nt < 8; nt++)
            #pragma unroll
            for (int rr = 0; rr < 2; rr++) {
                __half2 hv = __floats2half2_rn(s[nt][rr*2], s[nt][rr*2+1]);
                pf[nt >> 1][rr + 2*(nt & 1)] = *(uint32_t*)&hv;
            }

        // 6. O += P @ V ktp0
        #pragma unroll
        for (int nt = 0; nt < 16; nt++) {
            mma_f16(O[nt], pf[0], &vbf0[nt][0]);
            mma_f16(O[nt], pf[1], &vbf0[nt][2]);
        }

        // 7. prefetch next-iteration K (clamped)
        {
            int ktn = (kt < qt) ? kt + 1 : kt;
            #pragma unroll
            for (int ktp = 0; ktp < 2; ktp++)
                #pragma unroll
                for (int nt = 0; nt < 8; nt++)
                    *(uint4*)kbf[ktp][nt] =
                        *(const uint4*)(kbase + ((size_t)(ktn*8 + nt)*2 + ktp)*128);
        }

        // 8. O += P @ V ktp1
        #pragma unroll
        for (int nt = 0; nt < 16; nt++) {
            mma_f16(O[nt], pf[2], &vbf1[nt][0]);
            mma_f16(O[nt], pf[3], &vbf1[nt][2]);
        }
    }

    #pragma unroll
    for (int rr = 0; rr < 2; rr++) {
        float inv = 1.0f / l_[rr];
        size_t base = (((size_t)b*NH_ + h)*S_ + (size_t)qt*64 + w*16 + g + rr*8)*128;
        #pragma unroll
        for (int nt = 0; nt < 16; nt++)
            *(float2*)&ao[base + nt*8 + 2*t] =
                make_float2(O[nt][rr*2]*inv, O[nt][rr*2+1]*inv);
    }
}

// ---------------- differential combine + RMS norm -> fp16 A-frag layout ----------------
__global__ void __launch_bounds__(128) diff_rms_kernel(
    const float* __restrict__ ao, __half* __restrict__ outp) {
    __shared__ float red[4];
    int blk = blockIdx.x;
    int h  = blk & 15;
    int bs = blk >> 4;
    int b  = bs >> 11;
    int s  = bs & 2047;
    int t  = threadIdx.x;
    const float* a1 = ao + (((size_t)b*32 + h)*S_ + s)*128;
    const float* a2 = ao + (((size_t)b*32 + h + 16)*S_ + s)*128;
    float lam = g_lam;
    float x = a1[t] - lam*a2[t];
    float ss = x*x;
    #pragma unroll
    for (int off = 16; off >= 1; off >>= 1) ss += __shfl_xor_sync(0xffffffffu, ss, off);
    if ((t & 31) == 0) red[t >> 5] = ss;
    __syncthreads();
    float tot = red[0] + red[1] + red[2] + red[3];
    float r = rsqrtf(tot*(1.0f/128.0f) + 1e-6f);
    float li = 0.8f - 0.6f*expf(-0.3f);
    float val = (1.0f - li) * x * r;
    int row = bs, col = h*128 + t;
    int mt = row >> 4, rr = row & 15, kt = col >> 4, kk = col & 15;
    int reg = (rr >> 3) + 2*(kk >> 3);
    int lane = (rr & 7)*4 + ((kk & 7) >> 1);
    outp[((((size_t)mt*128 + kt)*32 + lane)*4 + reg)*2 + (kk & 1)] = __float2half_rn(val);
}

// ---------------- launch ----------------
extern "C" void kernel_launch(void* const* d_in, const int* in_sizes, int n_in,
                              void* d_out, int out_size) {
    const float* hs  = (const float*)d_in[0];
    const float* cs  = (const float*)d_in[1];
    const float* sn  = (const float*)d_in[2];
    const float* wq  = (const float*)d_in[4];
    const float* wk  = (const float*)d_in[5];
    const float* wv  = (const float*)d_in[6];
    const float* wo  = (const float*)d_in[7];
    const float* lq1 = (const float*)d_in[8];
    const float* lk1 = (const float*)d_in[9];
    const float* lq2 = (const float*)d_in[10];
    const float* lk2 = (const float*)d_in[11];
    float* out = (float*)d_out;

    float *qkvb, *aob;
    uint32_t *hsp, *attp, *wqkvp, *wop, *qfp, *kfp, *vfp;
    cudaGetSymbolAddress((void**)&qkvb, g_qkv);
    cudaGetSymbolAddress((void**)&aob,  g_ao);
    cudaGetSymbolAddress((void**)&hsp,  g_hsp);
    cudaGetSymbolAddress((void**)&attp, g_attp);
    cudaGetSymbolAddress((void**)&wqkvp, g_wqkvp);
    cudaGetSymbolAddress((void**)&wop,  g_wop);
    cudaGetSymbolAddress((void**)&qfp,  g_qf);
    cudaGetSymbolAddress((void**)&kfp,  g_kf);
    cudaGetSymbolAddress((void**)&vfp,  g_vf);

    // launch order: attn_direct is launch #4 -> profiled slot
    permAll<<<9216*1024/256, 256>>>(hs, wq, wk, wv, wo, hsp, wqkvp, wop);

    dim3 gqkv(3072/128, BS_/128);
    gemm_direct<<<gqkv, 256>>>(hsp, wqkvp, qkvb, 3072);

    fragqkv_k<<<BS_*1792/256, 256>>>(qkvb, cs, sn,
        (__half*)qfp, (__half*)kfp, (__half*)vfp);

    dim3 ga(S_/64, NH_, B_);
    attn_direct<<<ga, 128>>>(qfp, kfp, vfp, aob);

    lam_kernel<<<1, 32>>>(lq1, lk1, lq2, lk2);

    diff_rms_kernel<<<BS_*16, 128>>>(aob, (__half*)attp);

    dim3 go(2048/128, BS_/128);
    gemm_direct<<<go, 256>>>(attp, wop, out, 2048);
}